// round 16
// baseline (speedup 1.0000x reference)
#include <cuda_runtime.h>
#include <math.h>
#include <float.h>

#define NB 16
#define NA 5
#define NH 96
#define NW 96
#define MAXT 50
#define NCLS 40
#define CH (5 + NCLS)          // 45
#define NCELL (NB*NA*NH*NW)    // 737280
#define PLANE (NH*NW)          // 9216
#define MAXE 304               // >= 50 targets * 6 touched cells

#define SWEEP_BLOCKS ((NCELL + 255) / 256)   // 2880

// All-zero-default state (zero-initialized __device__ globals are correct on run 1)
// byte map: bit0 = mask, bit1 = (1 - conf_mask)   -> default 0 means mask=0, conf_mask=1
__device__ unsigned char g_mc[NCELL];
__device__ float g_tx[NCELL];
__device__ float g_ty[NCELL];
__device__ float g_tw[NCELL];
__device__ float g_th[NCELL];
__device__ int   g_tlabel[NCELL];
// previous replay's touched cells (for self-reset; deterministic across replays)
__device__ int   g_pcnt[NB];
__device__ int   g_pcell[NB * MAXE];
__device__ float g_nGT[NB];
__device__ float g_nC[NB];
// acc: 0 sx,1 sy,2 sw,3 sh,4 neg_sum,5 neg_cnt,6 pos_sum,7 nM,8 cls_sum,9 nProp
__device__ float g_acc[12];
__device__ int   g_done;

__global__ void k_build(const float* __restrict__ pred,
                        const float* __restrict__ target,
                        const int*   __restrict__ tsizes) {
    const int b = blockIdx.x;
    const int t = threadIdx.x;

    __shared__ int   s_gi[MAXT], s_gj[MAXT], s_best[MAXT], s_lbl[MAXT], s_cor[MAXT];
    __shared__ float s_tx[MAXT], s_ty[MAXT], s_tw[MAXT], s_th[MAXT];
    __shared__ unsigned s_ign[MAXT];

    // Idempotent accumulator zeroing (all blocks write the same values; sweep runs after)
    if (t < 10) g_acc[t] = 0.0f;
    if (t == 10) g_done = 0;

    // Reset this batch's cells touched by the PREVIOUS replay (empty on first run)
    {
        int pc = g_pcnt[b];
        for (int i = t; i < pc; i += 64) g_mc[g_pcell[b * MAXE + i]] = 0;
    }
    __syncthreads();   // order resets before thread 0's serial replay

    int ts = tsizes[b];
    if (ts > MAXT) ts = MAXT;

    const float AW[5] = {1.f, 2.f, 4.f, 2.f, 4.f};
    const float AH[5] = {1.f, 2.f, 4.f, 4.f, 2.f};

    if (t < ts) {
        const float* row = target + ((long)(b * MAXT + t)) * (13 + NCLS);
        float gx = row[0] * (1.0f / 16.0f);
        float gy = row[1] * (1.0f / 16.0f);
        float gh = row[3] * (1.0f / 16.0f);
        float gw = row[4] * (1.0f / 16.0f);
        int gi = (int)gx;
        int gj = (int)gy;

        // label = argmax over one-hot (first max)
        int lbl = 0; float bv = row[13];
        #pragma unroll
        for (int c = 1; c < NCLS; c++) {
            float v = row[13 + c];
            if (v > bv) { bv = v; lbl = c; }
        }

        // anchor IoUs
        float garea = (gw + 1.0f) * (gh + 1.0f);
        float best_iou = -1.0f; int best = 0; unsigned ign = 0u;
        #pragma unroll
        for (int a = 0; a < 5; a++) {
            float iw = fmaxf(fminf(gw, AW[a]) + 1.0f, 0.0f);
            float ih = fmaxf(fminf(gh, AH[a]) + 1.0f, 0.0f);
            float inter = iw * ih;
            float aa = (AW[a] + 1.0f) * (AH[a] + 1.0f);
            float iou = inter / (garea + aa - inter + 1e-16f);
            if (iou > 0.5f) ign |= (1u << a);
            if (iou > best_iou) { best_iou = iou; best = a; }  // first-max tie rule
        }

        s_gi[t] = gi; s_gj[t] = gj; s_best[t] = best; s_lbl[t] = lbl; s_ign[t] = ign;
        s_tx[t] = gx - (float)gi;
        s_ty[t] = gy - (float)gj;
        s_tw[t] = logf(gw / AW[best] + 1e-16f);
        s_th[t] = logf(gh / AH[best] + 1e-16f);

        // prediction at best cell (for nCorrect)
        long base = ((((long)b * NA + best) * NH + gj) * NW + gi) * CH;
        float pc = pred[base + 0];
        float x = pred[base + 1], y = pred[base + 2];
        float h = pred[base + 3], w = pred[base + 4];
        float px = x + (float)gi, py = y + (float)gj;
        float pw = expf(w) * AW[best];
        float ph = expf(h) * AH[best];

        float gx1 = gx - gw * 0.5f, gx2 = gx + gw * 0.5f;
        float gy1 = gy - gh * 0.5f, gy2 = gy + gh * 0.5f;
        float px1 = px - pw * 0.5f, px2 = px + pw * 0.5f;
        float py1 = py - ph * 0.5f, py2 = py + ph * 0.5f;
        float iw2 = fmaxf(fminf(gx2, px2) - fmaxf(gx1, px1) + 1.0f, 0.0f);
        float ih2 = fmaxf(fminf(gy2, py2) - fmaxf(gy1, py1) + 1.0f, 0.0f);
        float inter2 = iw2 * ih2;
        float ga = (gx2 - gx1 + 1.0f) * (gy2 - gy1 + 1.0f);
        float pa = (px2 - px1 + 1.0f) * (py2 - py1 + 1.0f);
        float iou2 = inter2 / (ga + pa - inter2 + 1e-16f);

        // pred class argmax (first max)
        int cb = 0; float cbv = pred[base + 5];
        #pragma unroll
        for (int c = 1; c < NCLS; c++) {
            float v = pred[base + 5 + c];
            if (v > cbv) { cbv = v; cb = c; }
        }
        s_cor[t] = (iou2 > 0.5f && cb == lbl && pc > 0.5f) ? 1 : 0;
    }
    __syncthreads();

    // Serial replay of map writes (ordering matters for collisions) + record touched cells
    if (t == 0) {
        int nC = 0, cnt = 0;
        for (int i = 0; i < ts; i++) {
            nC += s_cor[i];
            int gi = s_gi[i], gj = s_gj[i], best = s_best[i];
            int col = ((b * NA) * NH + gj) * NW + gi;   // anchor 0 cell index
            unsigned ign = s_ign[i];
            #pragma unroll
            for (int a = 0; a < 5; a++) {
                if ((ign >> a) & 1u) {
                    int cell = col + a * PLANE;
                    g_mc[cell] |= 2;                     // conf_mask -> 0 (keep mask bit)
                    g_pcell[b * MAXE + cnt++] = cell;
                }
            }
            int ib = col + best * PLANE;
            g_mc[ib] = 1;                                // mask=1, conf_mask=1
            g_pcell[b * MAXE + cnt++] = ib;
            g_tx[ib] = s_tx[i];
            g_ty[ib] = s_ty[i];
            g_tw[ib] = s_tw[i];
            g_th[ib] = s_th[i];
            g_tlabel[ib] = s_lbl[i];
        }
        g_pcnt[b] = cnt;
        g_nGT[b] = (float)ts;
        g_nC[b]  = (float)nC;
    }
}

__global__ void k_sweep(const float* __restrict__ pred, float* __restrict__ out) {
    const int cell = blockIdx.x * blockDim.x + threadIdx.x;

    float v[10]; // sx,sy,sw,sh,neg,negc,pos,nm,scls,nprop
    #pragma unroll
    for (int k = 0; k < 10; k++) v[k] = 0.0f;

    {
        unsigned int mc = g_mc[cell];
        float m   = (float)(mc & 1);
        int   cmX = (int)((mc >> 1) & 1);
        const float* p = pred + (long)cell * CH;
        float pc = p[0];
        float bce = fmaxf(pc, 0.0f) - pc * m + log1pf(expf(-fabsf(pc)));
        if ((mc & 1) == (unsigned)cmX) { v[4] = bce; v[5] = 1.0f; }   // cmf = (conf_mask != mask)
        v[6] = m * bce;
        v[7] = m;
        v[9] = (pc > 0.0f) ? 1.0f : 0.0f;
        if (mc & 1) {
            float x = p[1], y = p[2], h = p[3], w = p[4];
            float dx = x - g_tx[cell]; v[0] = dx * dx;
            float dy = y - g_ty[cell]; v[1] = dy * dy;
            float dw = w - g_tw[cell]; v[2] = dw * dw;
            float dh = h - g_th[cell]; v[3] = dh * dh;
            int lbl = g_tlabel[cell];
            float mx = -FLT_MAX;
            for (int c = 0; c < NCLS; c++) mx = fmaxf(mx, p[5 + c]);
            float s = 0.0f;
            for (int c = 0; c < NCLS; c++) s += expf(p[5 + c] - mx);
            v[8] = -(p[5 + lbl] - mx - logf(s));
        }
    }

    // block reduce 10 accumulators
    __shared__ float red[8][10];
    int lane = threadIdx.x & 31;
    int warp = threadIdx.x >> 5;
    #pragma unroll
    for (int k = 0; k < 10; k++) {
        float x = v[k];
        #pragma unroll
        for (int off = 16; off > 0; off >>= 1)
            x += __shfl_down_sync(0xFFFFFFFFu, x, off);
        if (lane == 0) red[warp][k] = x;
    }
    __syncthreads();
    if (warp == 0 && lane == 0) {
        #pragma unroll
        for (int k = 0; k < 10; k++) {
            float x = 0.0f;
            #pragma unroll
            for (int w = 0; w < 8; w++) x += red[w][k];
            if (x != 0.0f) atomicAdd(&g_acc[k], x);
        }
        __threadfence();
        int old = atomicAdd(&g_done, 1);
        if (old == SWEEP_BLOCKS - 1) {
            volatile float* A = g_acc;
            float nM = A[7];
            float lx = A[0] / nM;
            float ly = A[1] / nM;
            float lw = A[2] / nM;
            float lh = A[3] / nM;
            float lcoord = lx + ly + lw + lh;
            float lconf = A[4] / A[5] + A[6] / nM;
            float lcls = (1.0f / (float)NB) * A[8] / nM;
            float loss = lx + ly + lw + lh + lconf + lcls;
            float nGT = 0.0f, nC = 0.0f;
            for (int b = 0; b < NB; b++) { nGT += g_nGT[b]; nC += g_nC[b]; }
            float nP = A[9];
            out[0] = loss;
            out[1] = lcoord;
            out[2] = lconf;
            out[3] = lcls;
            out[4] = nC / fmaxf(nGT, 1.0f);
            out[5] = (nP > 0.0f) ? (nC / fmaxf(nP, 1.0f)) : 1.0f;
        }
    }
}

extern "C" void kernel_launch(void* const* d_in, const int* in_sizes, int n_in,
                              void* d_out, int out_size) {
    const float* pred   = (const float*)d_in[0];
    const float* target = (const float*)d_in[1];
    const int*   tsz    = (const int*)d_in[2];
    float* out = (float*)d_out;

    (void)in_sizes; (void)n_in; (void)out_size;

    k_build<<<NB, 64>>>(pred, target, tsz);
    k_sweep<<<SWEEP_BLOCKS, 256>>>(pred, out);
}